// round 13
// baseline (speedup 1.0000x reference)
#include <cuda_runtime.h>
#include <cuda_bf16.h>
#include <math.h>
#include <stdint.h>

// Problem dims (fixed by setup_inputs)
#define NB 8
#define NS 2048
#define DV 768
#define DA 512
#define NK 512
#define NR (NB*NS)            // 16384 rows
#define LAM 0.3f

// Fused GEMM tiling (mma.sync m16n8k16 bf16)
#define BM 128
#define BN 128
#define BK 32                 // bf16 k per chunk
#define NTH 512               // 16 warps, 4x4 grid, 32x32 warp tiles (R8 core)
#define ATILE 10240           // 128 rows * 80 B
#define STGB 20480            // one stage: A tile + B tile
#define NSTAGE 8              // power of two -> stage = c & 7
#define FUSED_SMEM (NSTAGE*STGB)   // 163840
#define NBLOCKS ((NK/BN)*(NR/BM)*2)   // 1024

// ---------------- device scratch; bf16 stored in uint4 arrays (16B-aligned) --
__device__ uint4 g_fV16u[(size_t)NR*DV/8];   // bf16 feat_vision
__device__ uint4 g_fA16u[(size_t)NR*DA/8];
__device__ uint4 g_sV16u[(size_t)NR*DV/8];   // bf16 smooth(feat_vision)
__device__ uint4 g_sA16u[(size_t)NR*DA/8];
__device__ uint4 g_pV16u[NK*DV/8];           // bf16 proto_vision
__device__ uint4 g_pA16u[NK*DA/8];
__device__ uint4 g_Mv16u[NK*DA/8];           // bf16 proto_v @ W_a2v
__device__ uint4 g_Ma16u[NK*DV/8];
__device__ float g_Mv[NK*DA];                // fp32 M (validated producer)
__device__ float g_Ma[NK*DV];
__device__ float g_partials[NBLOCKS];

#define G_FV16 ((__nv_bfloat16*)g_fV16u)
#define G_FA16 ((__nv_bfloat16*)g_fA16u)
#define G_SV16 ((__nv_bfloat16*)g_sV16u)
#define G_SA16 ((__nv_bfloat16*)g_sA16u)
#define G_PV16 ((__nv_bfloat16*)g_pV16u)
#define G_PA16 ((__nv_bfloat16*)g_pA16u)
#define G_MV16 ((__nv_bfloat16*)g_Mv16u)
#define G_MA16 ((__nv_bfloat16*)g_Ma16u)

// ---------------- helpers ----------------
__device__ __forceinline__ uint32_t smem_u32(const void* p) {
    uint32_t a;
    asm("{ .reg .u64 t; cvta.to.shared.u64 t, %1; cvt.u32.u64 %0, t; }" : "=r"(a) : "l"(p));
    return a;
}
__device__ __forceinline__ void cp16(uint32_t dst, const void* src) {
    asm volatile("cp.async.cg.shared.global [%0], [%1], 16;" :: "r"(dst), "l"(src) : "memory");
}
__device__ __forceinline__ void cp_commit() {
    asm volatile("cp.async.commit_group;" ::: "memory");
}
__device__ __forceinline__ void cp_wait1() {
    asm volatile("cp.async.wait_group 1;" ::: "memory");
}
__device__ __forceinline__ void cp_wait0() {
    asm volatile("cp.async.wait_group 0;" ::: "memory");
}
__device__ __forceinline__ void ldsm4(uint32_t* r, uint32_t addr) {
    asm volatile("ldmatrix.sync.aligned.m8n8.x4.shared.b16 {%0,%1,%2,%3}, [%4];"
                 : "=r"(r[0]), "=r"(r[1]), "=r"(r[2]), "=r"(r[3]) : "r"(addr));
}
__device__ __forceinline__ void ldsm2(uint32_t* r, uint32_t addr) {
    asm volatile("ldmatrix.sync.aligned.m8n8.x2.shared.b16 {%0,%1}, [%2];"
                 : "=r"(r[0]), "=r"(r[1]) : "r"(addr));
}
__device__ __forceinline__ void mma16816(float* c, const uint32_t* a, const uint32_t* b) {
    asm volatile(
        "mma.sync.aligned.m16n8k16.row.col.f32.bf16.bf16.f32 "
        "{%0,%1,%2,%3}, {%4,%5,%6,%7}, {%8,%9}, {%0,%1,%2,%3};"
        : "+f"(c[0]), "+f"(c[1]), "+f"(c[2]), "+f"(c[3])
        : "r"(a[0]), "r"(a[1]), "r"(a[2]), "r"(a[3]), "r"(b[0]), "r"(b[1]));
}
__device__ __forceinline__ uint2 cvt4(float4 v) {
    __nv_bfloat162 lo = __floats2bfloat162_rn(v.x, v.y);
    __nv_bfloat162 hi = __floats2bfloat162_rn(v.z, v.w);
    uint2 r;
    r.x = *reinterpret_cast<uint32_t*>(&lo);
    r.y = *reinterpret_cast<uint32_t*>(&hi);
    return r;
}

// ---------------------------------------------------------------------------
// Both smooth+cvt passes in ONE launch (R11-validated).
// ---------------------------------------------------------------------------
__global__ void smooth_all_kernel(const float* __restrict__ fvin,
                                  const float* __restrict__ fain)
{
    const int vz = (blockIdx.z == 0);            // z=0: vision, z=1: audio
    const float* f = vz ? fvin : fain;
    const int D = vz ? DV : DA;
    uint2* __restrict__ s16 = reinterpret_cast<uint2*>(vz ? G_SV16 : G_SA16);
    uint2* __restrict__ f16 = reinterpret_cast<uint2*>(vz ? G_FV16 : G_FA16);
    const float4* __restrict__ fv = reinterpret_cast<const float4*>(f);
    const int D4 = D >> 2;
    const long total = (long)NR * D4;
    const float inv3 = 1.0f / 3.0f;
    for (long i = (long)blockIdx.x*blockDim.x + threadIdx.x; i < total;
         i += (long)gridDim.x*blockDim.x) {
        long row = i / D4;
        int s = (int)(row % NS);
        float4 c = fv[i];
        float4 r;
        if (s == 0) {
            float4 n = fv[i + D4];
            r.x=(c.x+n.x)*0.5f; r.y=(c.y+n.y)*0.5f;
            r.z=(c.z+n.z)*0.5f; r.w=(c.w+n.w)*0.5f;
        } else if (s == NS-1) {
            float4 p = fv[i - D4];
            r.x=(c.x+p.x)*0.5f; r.y=(c.y+p.y)*0.5f;
            r.z=(c.z+p.z)*0.5f; r.w=(c.w+p.w)*0.5f;
        } else {
            float4 p = fv[i - D4];
            float4 n = fv[i + D4];
            r.x=(p.x+c.x+n.x)*inv3; r.y=(p.y+c.y+n.y)*inv3;
            r.z=(p.z+c.z+n.z)*inv3; r.w=(p.w+c.w+n.w)*inv3;
        }
        s16[i] = cvt4(r);
        f16[i] = cvt4(c);
    }
}

// ---------------------------------------------------------------------------
// Both M = P @ W GEMMs in ONE launch (R11-validated).
// ---------------------------------------------------------------------------
__global__ void proto_all_kernel(const float* __restrict__ pv,
                                 const float* __restrict__ pa,
                                 const float* __restrict__ wav,
                                 const float* __restrict__ wva)
{
    const int za = (blockIdx.z != 0);
    if (!za && blockIdx.x >= DA/16) return;      // uniform per block, pre-sync
    const float* __restrict__ P = za ? pa : pv;
    const float* __restrict__ W = za ? wva : wav;
    const int D = za ? DA : DV;
    const int C = za ? DV : DA;
    float* __restrict__ Cout = za ? g_Ma : g_Mv;

    __shared__ float As[16][16];
    __shared__ float Ws[16][17];
    int tx = threadIdx.x, ty = threadIdx.y;
    int row = blockIdx.y*16 + ty;
    int col = blockIdx.x*16 + tx;
    float acc = 0.f;
    for (int d0 = 0; d0 < D; d0 += 16) {
        As[ty][tx] = P[row*D + d0 + tx];
        Ws[ty][tx] = W[(d0+ty)*C + col];
        __syncthreads();
        #pragma unroll
        for (int kk = 0; kk < 16; kk++) acc += As[ty][kk]*Ws[kk][tx];
        __syncthreads();
    }
    Cout[row*C + col] = acc;
}

// ---------------------------------------------------------------------------
// All fp32->bf16 conversions in ONE launch (R9-validated).
// ---------------------------------------------------------------------------
__global__ void cvt_all_kernel(const float* __restrict__ pv, const float* __restrict__ pa)
{
    const int nPV = NK*DV, nPA = NK*DA, nMV = NK*DA, nMA = NK*DV;
    const int total = nPV + nPA + nMV + nMA;
    for (int i = blockIdx.x*blockDim.x + threadIdx.x; i < total; i += gridDim.x*blockDim.x) {
        if (i < nPV)                      G_PV16[i] = __float2bfloat16(pv[i]);
        else if (i < nPV+nPA)             G_PA16[i-nPV] = __float2bfloat16(pa[i-nPV]);
        else if (i < nPV+nPA+nMV)         G_MV16[i-nPV-nPA] = __float2bfloat16(g_Mv[i-nPV-nPA]);
        else                              G_MA16[i-nPV-nPA-nMV] = __float2bfloat16(g_Ma[i-nPV-nPA-nMV]);
    }
}

// ---------------------------------------------------------------------------
// Fused HMMA energy kernel. gridDim = (NK/BN, NR/BM, 2).
// R13: R8-validated 16-warp core (4x4 warp grid, 32x32 tiles) under the
// R12-validated loop structure (split phases, static accs, &7 ring, exact waits).
// ---------------------------------------------------------------------------
extern __shared__ char dsm[];

__global__ __launch_bounds__(NTH)
void fused_energy_kernel()
{
    __shared__ float red_s[16];

    const int tid = threadIdx.x;
    const int wid = tid >> 5;
    const int lane = tid & 31;
    const int z = blockIdx.z;
    const long row0 = (long)blockIdx.y * BM;
    const long col0 = (long)blockIdx.x * BN;

    const __nv_bfloat16 *A1, *B1, *A2, *B2;
    int D1, D2;
    if (z == 0) { A1 = G_FV16; B1 = G_PV16; D1 = DV; A2 = G_SA16; B2 = G_MV16; D2 = DA; }
    else        { A1 = G_FA16; B1 = G_PA16; D1 = DA; A2 = G_SV16; B2 = G_MA16; D2 = DV; }
    const int n1 = D1 / BK;          // 24 or 16, even
    const int nch = n1 + D2 / BK;    // 40

    const uint32_t base0 = smem_u32(dsm);

    // 512 threads: each loads 1 A unit + 1 B unit (512 x 16B units per tile)
    auto load_chunk = [&](int c, int stage) {
        const __nv_bfloat16 *A, *B; int D, k0;
        if (c < n1) { A = A1; B = B1; D = D1; k0 = c * BK; }
        else        { A = A2; B = B2; D = D2; k0 = (c - n1) * BK; }
        uint32_t base = base0 + stage * STGB;
        int row = tid >> 2, seg = tid & 3;
        uint32_t d = base + (uint32_t)(row * 80 + seg * 16);
        cp16(d,         A + (row0 + row) * D + k0 + seg * 8);
        cp16(d + ATILE, B + (col0 + row) * D + k0 + seg * 8);
    };
    auto load_pair = [&](int c) {
        load_chunk(c, c & (NSTAGE-1));
        if (c + 1 < nch) load_chunk(c + 1, (c + 1) & (NSTAGE-1));
        cp_commit();
    };

    const int wm = (wid >> 2) * 32;   // warp row base (0,32,64,96)
    const int wn = (wid & 3) * 32;    // warp col base
    const int arow = wm + (lane & 7) + ((lane >> 3) & 1) * 8;
    const int acol = (lane >> 4) * 16;           // byte offset (k-half)
    const int l2 = lane & 15;
    const int brow = wn + (l2 & 7);
    const int bcol = ((l2 >> 3) & 1) * 16;

    auto compute_chunk = [&](int stage, float (&acc)[2][4][4]) {
        uint32_t sA = base0 + stage * STGB;
        uint32_t sB = sA + ATILE;
        #pragma unroll
        for (int ks = 0; ks < 2; ks++) {
            uint32_t a[2][4];
            #pragma unroll
            for (int i = 0; i < 2; i++)
                ldsm4(a[i], sA + (uint32_t)((arow + i * 16) * 80 + acol + ks * 32));
            uint32_t b[4][2];
            #pragma unroll
            for (int j = 0; j < 4; j++)
                ldsm2(b[j], sB + (uint32_t)((brow + j * 8) * 80 + bcol + ks * 32));
            #pragma unroll
            for (int i = 0; i < 2; i++)
                #pragma unroll
                for (int j = 0; j < 4; j++)
                    mma16816(acc[i][j], a[i], b[j]);
        }
    };

    float acc1[2][4][4] = {};
    float acc2[2][4][4] = {};

    load_pair(0);
    load_pair(2);

    // phase 1: chunks [0, n1) -> acc1 (n1 even; pairs never straddle)
    for (int c = 0; c < n1; c += 2) {
        cp_wait1();                      // c+2 < nch always here
        __syncthreads();
        if (c + 4 < nch) load_pair(c + 4);
        compute_chunk(c & (NSTAGE-1), acc1);
        compute_chunk((c + 1) & (NSTAGE-1), acc1);
    }
    // phase 2: chunks [n1, nch) -> acc2
    for (int c = n1; c < nch; c += 2) {
        if (c + 2 < nch) cp_wait1(); else cp_wait0();
        __syncthreads();
        if (c + 4 < nch) load_pair(c + 4);
        compute_chunk(c & (NSTAGE-1), acc2);
        compute_chunk((c + 1) & (NSTAGE-1), acc2);
    }

    float local = 0.f;
    #pragma unroll
    for (int i = 0; i < 2; i++)
        #pragma unroll
        for (int j = 0; j < 4; j++)
            #pragma unroll
            for (int r = 0; r < 4; r++) {
                float c1 = acc1[i][j][r];
                float c2 = acc2[i][j][r];
                float sal = LAM * c2 * c2 + (1.0f - LAM) * c1 * c1;
                float x = sal * c1;
                local += fmaxf(x, 0.f) + log1pf(__expf(-fabsf(x)));
            }
    #pragma unroll
    for (int o = 16; o > 0; o >>= 1)
        local += __shfl_xor_sync(0xFFFFFFFF, local, o);
    if (lane == 0) red_s[wid] = local;
    __syncthreads();
    if (tid == 0) {
        float s = 0.f;
        #pragma unroll
        for (int w = 0; w < 16; w++) s += red_s[w];
        g_partials[(z * gridDim.y + blockIdx.y) * gridDim.x + blockIdx.x] = s;
    }
}

// ---------------------------------------------------------------------------
// Deterministic final reduction
// ---------------------------------------------------------------------------
__global__ void final_reduce_kernel(float* __restrict__ out)
{
    __shared__ double red[256];
    double s = 0.0;
    for (int i = threadIdx.x; i < NBLOCKS; i += 256) s += (double)g_partials[i];
    red[threadIdx.x] = s;
    __syncthreads();
    for (int st = 128; st > 0; st >>= 1) {
        if (threadIdx.x < st) red[threadIdx.x] += red[threadIdx.x + st];
        __syncthreads();
    }
    if (threadIdx.x == 0) out[0] = (float)(-red[0]);
}

// ---------------------------------------------------------------------------
extern "C" void kernel_launch(void* const* d_in, const int* in_sizes, int n_in,
                              void* d_out, int out_size)
{
    const float* fv  = (const float*)d_in[0];   // (8,2048,768)
    const float* fa  = (const float*)d_in[1];   // (8,2048,512)
    const float* pv  = (const float*)d_in[2];   // (512,768)
    const float* pa  = (const float*)d_in[3];   // (512,512)
    const float* wav = (const float*)d_in[4];   // (768,512)
    const float* wva = (const float*)d_in[5];   // (512,768)
    float* out = (float*)d_out;

    cudaFuncSetAttribute(fused_energy_kernel,
                         cudaFuncAttributeMaxDynamicSharedMemorySize, FUSED_SMEM);

    smooth_all_kernel<<<dim3(2048, 1, 2), 256>>>(fv, fa);                         // 0
    proto_all_kernel<<<dim3(DV/16, NK/16, 2), dim3(16,16)>>>(pv, pa, wav, wva);   // 1
    cvt_all_kernel<<<1024, 256>>>(pv, pa);                                        // 2

    fused_energy_kernel<<<dim3(NK/BN, NR/BM, 2), NTH, FUSED_SMEM>>>();            // 3

    final_reduce_kernel<<<1, 256>>>(out);                                         // 4
}

// round 15
// speedup vs baseline: 1.0966x; 1.0966x over previous
#include <cuda_runtime.h>
#include <cuda_bf16.h>
#include <math.h>
#include <stdint.h>

// Problem dims (fixed by setup_inputs)
#define NB 8
#define NS 2048
#define DV 768
#define DA 512
#define NK 512
#define NR (NB*NS)            // 16384 rows
#define LAM 0.3f

// Fused GEMM tiling (mma.sync m16n8k16 bf16) -- R12 core, phase-staged accs
#define BM 128
#define BN 128
#define BK 32                 // bf16 k per chunk
#define NTH 256               // 8 warps, 2x4 grid, 64x32 warp tiles
#define ATILE 10240           // 128 rows * 80 B
#define STGB 20480            // one stage: A tile + B tile
#define NSTAGE 4              // ring invariant: pairs {c, c+2} resident only
#define C2BUF (NSTAGE*STGB)   // 81920: offset of c2 staging buffer (32 KB)
#define FUSED_SMEM (C2BUF + 32*1024)   // 114688 -> 2 CTAs/SM
#define NBLOCKS ((NK/BN)*(NR/BM)*2)    // 1024

// ---------------- device scratch; bf16 stored in uint4 arrays (16B-aligned) --
__device__ uint4 g_fV16u[(size_t)NR*DV/8];   // bf16 feat_vision
__device__ uint4 g_fA16u[(size_t)NR*DA/8];
__device__ uint4 g_sV16u[(size_t)NR*DV/8];   // bf16 smooth(feat_vision)
__device__ uint4 g_sA16u[(size_t)NR*DA/8];
__device__ uint4 g_pV16u[NK*DV/8];           // bf16 proto_vision
__device__ uint4 g_pA16u[NK*DA/8];
__device__ uint4 g_Mv16u[NK*DA/8];           // bf16 proto_v @ W_a2v
__device__ uint4 g_Ma16u[NK*DV/8];
__device__ float g_Mv[NK*DA];                // fp32 M (validated producer)
__device__ float g_Ma[NK*DV];
__device__ float g_partials[NBLOCKS];

#define G_FV16 ((__nv_bfloat16*)g_fV16u)
#define G_FA16 ((__nv_bfloat16*)g_fA16u)
#define G_SV16 ((__nv_bfloat16*)g_sV16u)
#define G_SA16 ((__nv_bfloat16*)g_sA16u)
#define G_PV16 ((__nv_bfloat16*)g_pV16u)
#define G_PA16 ((__nv_bfloat16*)g_pA16u)
#define G_MV16 ((__nv_bfloat16*)g_Mv16u)
#define G_MA16 ((__nv_bfloat16*)g_Ma16u)

// ---------------- helpers ----------------
__device__ __forceinline__ uint32_t smem_u32(const void* p) {
    uint32_t a;
    asm("{ .reg .u64 t; cvta.to.shared.u64 t, %1; cvt.u32.u64 %0, t; }" : "=r"(a) : "l"(p));
    return a;
}
__device__ __forceinline__ void cp16(uint32_t dst, const void* src) {
    asm volatile("cp.async.cg.shared.global [%0], [%1], 16;" :: "r"(dst), "l"(src) : "memory");
}
__device__ __forceinline__ void cp_commit() {
    asm volatile("cp.async.commit_group;" ::: "memory");
}
__device__ __forceinline__ void cp_wait1() {
    asm volatile("cp.async.wait_group 1;" ::: "memory");
}
__device__ __forceinline__ void cp_wait0() {
    asm volatile("cp.async.wait_group 0;" ::: "memory");
}
__device__ __forceinline__ void ldsm4(uint32_t* r, uint32_t addr) {
    asm volatile("ldmatrix.sync.aligned.m8n8.x4.shared.b16 {%0,%1,%2,%3}, [%4];"
                 : "=r"(r[0]), "=r"(r[1]), "=r"(r[2]), "=r"(r[3]) : "r"(addr));
}
__device__ __forceinline__ void ldsm2(uint32_t* r, uint32_t addr) {
    asm volatile("ldmatrix.sync.aligned.m8n8.x2.shared.b16 {%0,%1}, [%2];"
                 : "=r"(r[0]), "=r"(r[1]) : "r"(addr));
}
__device__ __forceinline__ void mma16816(float* c, const uint32_t* a, const uint32_t* b) {
    asm volatile(
        "mma.sync.aligned.m16n8k16.row.col.f32.bf16.bf16.f32 "
        "{%0,%1,%2,%3}, {%4,%5,%6,%7}, {%8,%9}, {%0,%1,%2,%3};"
        : "+f"(c[0]), "+f"(c[1]), "+f"(c[2]), "+f"(c[3])
        : "r"(a[0]), "r"(a[1]), "r"(a[2]), "r"(a[3]), "r"(b[0]), "r"(b[1]));
}
__device__ __forceinline__ uint2 cvt4(float4 v) {
    __nv_bfloat162 lo = __floats2bfloat162_rn(v.x, v.y);
    __nv_bfloat162 hi = __floats2bfloat162_rn(v.z, v.w);
    uint2 r;
    r.x = *reinterpret_cast<uint32_t*>(&lo);
    r.y = *reinterpret_cast<uint32_t*>(&hi);
    return r;
}

// ---------------------------------------------------------------------------
// Both smooth+cvt passes in ONE launch (R11-validated).
// ---------------------------------------------------------------------------
__global__ void smooth_all_kernel(const float* __restrict__ fvin,
                                  const float* __restrict__ fain)
{
    const int vz = (blockIdx.z == 0);            // z=0: vision, z=1: audio
    const float* f = vz ? fvin : fain;
    const int D = vz ? DV : DA;
    uint2* __restrict__ s16 = reinterpret_cast<uint2*>(vz ? G_SV16 : G_SA16);
    uint2* __restrict__ f16 = reinterpret_cast<uint2*>(vz ? G_FV16 : G_FA16);
    const float4* __restrict__ fv = reinterpret_cast<const float4*>(f);
    const int D4 = D >> 2;
    const long total = (long)NR * D4;
    const float inv3 = 1.0f / 3.0f;
    for (long i = (long)blockIdx.x*blockDim.x + threadIdx.x; i < total;
         i += (long)gridDim.x*blockDim.x) {
        long row = i / D4;
        int s = (int)(row % NS);
        float4 c = fv[i];
        float4 r;
        if (s == 0) {
            float4 n = fv[i + D4];
            r.x=(c.x+n.x)*0.5f; r.y=(c.y+n.y)*0.5f;
            r.z=(c.z+n.z)*0.5f; r.w=(c.w+n.w)*0.5f;
        } else if (s == NS-1) {
            float4 p = fv[i - D4];
            r.x=(c.x+p.x)*0.5f; r.y=(c.y+p.y)*0.5f;
            r.z=(c.z+p.z)*0.5f; r.w=(c.w+p.w)*0.5f;
        } else {
            float4 p = fv[i - D4];
            float4 n = fv[i + D4];
            r.x=(p.x+c.x+n.x)*inv3; r.y=(p.y+c.y+n.y)*inv3;
            r.z=(p.z+c.z+n.z)*inv3; r.w=(p.w+c.w+n.w)*inv3;
        }
        s16[i] = cvt4(r);
        f16[i] = cvt4(c);
    }
}

// ---------------------------------------------------------------------------
// Both M = P @ W GEMMs in ONE launch (R11-validated).
// ---------------------------------------------------------------------------
__global__ void proto_all_kernel(const float* __restrict__ pv,
                                 const float* __restrict__ pa,
                                 const float* __restrict__ wav,
                                 const float* __restrict__ wva)
{
    const int za = (blockIdx.z != 0);
    if (!za && blockIdx.x >= DA/16) return;      // uniform per block, pre-sync
    const float* __restrict__ P = za ? pa : pv;
    const float* __restrict__ W = za ? wva : wav;
    const int D = za ? DA : DV;
    const int C = za ? DV : DA;
    float* __restrict__ Cout = za ? g_Ma : g_Mv;

    __shared__ float As[16][16];
    __shared__ float Ws[16][17];
    int tx = threadIdx.x, ty = threadIdx.y;
    int row = blockIdx.y*16 + ty;
    int col = blockIdx.x*16 + tx;
    float acc = 0.f;
    for (int d0 = 0; d0 < D; d0 += 16) {
        As[ty][tx] = P[row*D + d0 + tx];
        Ws[ty][tx] = W[(d0+ty)*C + col];
        __syncthreads();
        #pragma unroll
        for (int kk = 0; kk < 16; kk++) acc += As[ty][kk]*Ws[kk][tx];
        __syncthreads();
    }
    Cout[row*C + col] = acc;
}

// ---------------------------------------------------------------------------
// All fp32->bf16 conversions in ONE launch (R9-validated).
// ---------------------------------------------------------------------------
__global__ void cvt_all_kernel(const float* __restrict__ pv, const float* __restrict__ pa)
{
    const int nPV = NK*DV, nPA = NK*DA, nMV = NK*DA, nMA = NK*DV;
    const int total = nPV + nPA + nMV + nMA;
    for (int i = blockIdx.x*blockDim.x + threadIdx.x; i < total; i += gridDim.x*blockDim.x) {
        if (i < nPV)                      G_PV16[i] = __float2bfloat16(pv[i]);
        else if (i < nPV+nPA)             G_PA16[i-nPV] = __float2bfloat16(pa[i-nPV]);
        else if (i < nPV+nPA+nMV)         G_MV16[i-nPV-nPA] = __float2bfloat16(g_Mv[i-nPV-nPA]);
        else                              G_MA16[i-nPV-nPA-nMV] = __float2bfloat16(g_Ma[i-nPV-nPA-nMV]);
    }
}

// ---------------------------------------------------------------------------
// Fused HMMA energy kernel. gridDim = (NK/BN, NR/BM, 2).
// R15 = R14 with CORRECT ring discipline: load_pair(c+4) issued AFTER both
// computes of pair c (behind a barrier). Resident pairs at compute: {c, c+2}
// -> exactly 4 stages. Phase-staged single acc set (cross -> bf16 smem,
// intra -> regs). NSTAGE=4, 112 KB smem, launch_bounds(256,2) -> 2 CTAs/SM.
// ---------------------------------------------------------------------------
extern __shared__ char dsm[];

__global__ __launch_bounds__(NTH, 2)
void fused_energy_kernel()
{
    __shared__ float red_s[8];

    const int tid = threadIdx.x;
    const int wid = tid >> 5;
    const int lane = tid & 31;
    const int z = blockIdx.z;
    const long row0 = (long)blockIdx.y * BM;
    const long col0 = (long)blockIdx.x * BN;

    // phase-1 (cross) sources, phase-2 (intra) sources
    const __nv_bfloat16 *Ax, *Bx, *Ai, *Bi;
    int Dx, Di;
    if (z == 0) { Ax = G_SA16; Bx = G_MV16; Dx = DA; Ai = G_FV16; Bi = G_PV16; Di = DV; }
    else        { Ax = G_SV16; Bx = G_MA16; Dx = DV; Ai = G_FA16; Bi = G_PA16; Di = DA; }
    const int n1 = Dx / BK;          // cross chunks (16 or 24, even)
    const int nch = n1 + Di / BK;    // 40

    const uint32_t base0 = smem_u32(dsm);

    auto load_chunk = [&](int c, int stage) {
        const __nv_bfloat16 *A, *B; int D, k0;
        if (c < n1) { A = Ax; B = Bx; D = Dx; k0 = c * BK; }
        else        { A = Ai; B = Bi; D = Di; k0 = (c - n1) * BK; }
        uint32_t base = base0 + stage * STGB;
        #pragma unroll
        for (int r = 0; r < 2; r++) {
            int u = tid + r * 256;
            int row = u >> 2, seg = u & 3;
            uint32_t d = base + (uint32_t)(row * 80 + seg * 16);
            cp16(d,         A + (row0 + row) * D + k0 + seg * 8);
            cp16(d + ATILE, B + (col0 + row) * D + k0 + seg * 8);
        }
    };
    auto load_pair = [&](int c) {
        load_chunk(c, c & (NSTAGE-1));
        if (c + 1 < nch) load_chunk(c + 1, (c + 1) & (NSTAGE-1));
        cp_commit();
    };

    const int wm = (wid >> 2) * 64;   // warp row base
    const int wn = (wid & 3) * 32;    // warp col base
    const int arow = wm + (lane & 7) + ((lane >> 3) & 1) * 8;
    const int acol = (lane >> 4) * 16;           // byte offset (k-half)
    const int l2 = lane & 15;
    const int brow = wn + (l2 & 7);
    const int bcol = ((l2 >> 3) & 1) * 16;

    auto compute_chunk = [&](int stage, float (&acc)[4][4][4]) {
        uint32_t sA = base0 + stage * STGB;
        uint32_t sB = sA + ATILE;
        #pragma unroll
        for (int ks = 0; ks < 2; ks++) {
            uint32_t a[4][4];
            #pragma unroll
            for (int i = 0; i < 4; i++)
                ldsm4(a[i], sA + (uint32_t)((arow + i * 16) * 80 + acol + ks * 32));
            uint32_t b[4][2];
            #pragma unroll
            for (int j = 0; j < 4; j++)
                ldsm2(b[j], sB + (uint32_t)((brow + j * 8) * 80 + bcol + ks * 32));
            #pragma unroll
            for (int i = 0; i < 4; i++)
                #pragma unroll
                for (int j = 0; j < 4; j++)
                    mma16816(acc[i][j], a[i], b[j]);
        }
    };

    float acc[4][4][4] = {};

    load_pair(0);
    load_pair(2);

    // One iteration: wait pair c, compute both chunks, barrier, THEN issue
    // pair c+4 into the stages just vacated. Resident: {c, c+2} = 4 stages.
    auto pipe_step = [&](int c, float (&a)[4][4][4]) {
        if (c + 2 < nch) cp_wait1(); else cp_wait0();
        __syncthreads();                  // pair c visible to all warps
        compute_chunk(c & (NSTAGE-1), a);
        if (c + 1 < nch) compute_chunk((c + 1) & (NSTAGE-1), a);
        __syncthreads();                  // all warps done reading pair c
        if (c + 4 < nch) load_pair(c + 4);
    };

    // ---- phase 1: cross chunks [0, n1) -> acc, staged as c2 ----
    for (int c = 0; c < n1; c += 2) pipe_step(c, acc);

    // ---- stage c2 = cross results as bf16 (thread-private slots) ----
    {
        uint32_t* c2b = reinterpret_cast<uint32_t*>(dsm + C2BUF) + tid * 32;
        int s = 0;
        #pragma unroll
        for (int i = 0; i < 4; i++)
            #pragma unroll
            for (int j = 0; j < 4; j++)
                #pragma unroll
                for (int r = 0; r < 4; r += 2) {
                    __nv_bfloat162 p = __floats2bfloat162_rn(acc[i][j][r], acc[i][j][r+1]);
                    c2b[s++] = *reinterpret_cast<uint32_t*>(&p);
                }
        #pragma unroll
        for (int i = 0; i < 4; i++)
            #pragma unroll
            for (int j = 0; j < 4; j++)
                #pragma unroll
                for (int r = 0; r < 4; r++) acc[i][j][r] = 0.f;
    }

    // ---- phase 2: intra chunks [n1, nch) -> acc ----
    for (int c = n1; c < nch; c += 2) pipe_step(c, acc);

    // ---- epilogue: c1 = acc (regs), c2 = staged bf16 ----
    float local = 0.f;
    {
        const uint32_t* c2b = reinterpret_cast<const uint32_t*>(dsm + C2BUF) + tid * 32;
        int s = 0;
        #pragma unroll
        for (int i = 0; i < 4; i++)
            #pragma unroll
            for (int j = 0; j < 4; j++)
                #pragma unroll
                for (int r = 0; r < 4; r += 2) {
                    uint32_t pk = c2b[s++];
                    __nv_bfloat162 p = *reinterpret_cast<const __nv_bfloat162*>(&pk);
                    float c2a = __bfloat162float(p.x);
                    float c2bv = __bfloat162float(p.y);
                    float c1a = acc[i][j][r];
                    float c1b = acc[i][j][r+1];
                    float sala = LAM * c2a * c2a + (1.0f - LAM) * c1a * c1a;
                    float salb = LAM * c2bv * c2bv + (1.0f - LAM) * c1b * c1b;
                    float xa = sala * c1a;
                    float xb = salb * c1b;
                    local += fmaxf(xa, 0.f) + log1pf(__expf(-fabsf(xa)));
                    local += fmaxf(xb, 0.f) + log1pf(__expf(-fabsf(xb)));
                }
    }
    #pragma unroll
    for (int o = 16; o > 0; o >>= 1)
        local += __shfl_xor_sync(0xFFFFFFFF, local, o);
    if (lane == 0) red_s[wid] = local;
    __syncthreads();
    if (tid == 0) {
        float s = 0.f;
        #pragma unroll
        for (int w = 0; w < 8; w++) s += red_s[w];
        g_partials[(z * gridDim.y + blockIdx.y) * gridDim.x + blockIdx.x] = s;
    }
}

// ---------------------------------------------------------------------------
// Deterministic final reduction
// ---------------------------------------------------------------------------
__global__ void final_reduce_kernel(float* __restrict__ out)
{
    __shared__ double red[256];
    double s = 0.0;
    for (int i = threadIdx.x; i < NBLOCKS; i += 256) s += (double)g_partials[i];
    red[threadIdx.x] = s;
    __syncthreads();
    for (int st = 128; st > 0; st >>= 1) {
        if (threadIdx.x < st) red[threadIdx.x] += red[threadIdx.x + st];
        __syncthreads();
    }
    if (threadIdx.x == 0) out[0] = (float)(-red[0]);
}

// ---------------------------------------------------------------------------
extern "C" void kernel_launch(void* const* d_in, const int* in_sizes, int n_in,
                              void* d_out, int out_size)
{
    const float* fv  = (const float*)d_in[0];   // (8,2048,768)
    const float* fa  = (const float*)d_in[1];   // (8,2048,512)
    const float* pv  = (const float*)d_in[2];   // (512,768)
    const float* pa  = (const float*)d_in[3];   // (512,512)
    const float* wav = (const float*)d_in[4];   // (768,512)
    const float* wva = (const float*)d_in[5];   // (512,768)
    float* out = (float*)d_out;

    cudaFuncSetAttribute(fused_energy_kernel,
                         cudaFuncAttributeMaxDynamicSharedMemorySize, FUSED_SMEM);

    smooth_all_kernel<<<dim3(2048, 1, 2), 256>>>(fv, fa);                         // 0
    proto_all_kernel<<<dim3(DV/16, NK/16, 2), dim3(16,16)>>>(pv, pa, wav, wva);   // 1
    cvt_all_kernel<<<1024, 256>>>(pv, pa);                                        // 2

    fused_energy_kernel<<<dim3(NK/BN, NR/BM, 2), NTH, FUSED_SMEM>>>();            // 3

    final_reduce_kernel<<<1, 256>>>(out);                                         // 4
}

// round 16
// speedup vs baseline: 1.1352x; 1.0352x over previous
#include <cuda_runtime.h>
#include <cuda_bf16.h>
#include <math.h>
#include <stdint.h>

// Problem dims (fixed by setup_inputs)
#define NB 8
#define NS 2048
#define DV 768
#define DA 512
#define NK 512
#define NR (NB*NS)            // 16384 rows
#define LAM 0.3f

// Fused GEMM tiling (mma.sync m16n8k16 bf16) -- R15-validated
#define BM 128
#define BN 128
#define BK 32                 // bf16 k per chunk
#define NTH 256               // 8 warps, 2x4 grid, 64x32 warp tiles
#define ATILE 10240           // 128 rows * 80 B
#define STGB 20480            // one stage: A tile + B tile
#define NSTAGE 4              // ring invariant: pairs {c, c+2} resident only
#define C2BUF (NSTAGE*STGB)   // 81920: offset of c2 staging buffer (32 KB)
#define FUSED_SMEM (C2BUF + 32*1024)   // 114688 -> 2 CTAs/SM
#define NBLOCKS ((NK/BN)*(NR/BM)*2)    // 1024

// ---------------- device scratch; bf16 stored in uint4 arrays (16B-aligned) --
__device__ uint4 g_fV16u[(size_t)NR*DV/8];   // bf16 feat_vision
__device__ uint4 g_fA16u[(size_t)NR*DA/8];
__device__ uint4 g_sV16u[(size_t)NR*DV/8];   // bf16 smooth(feat_vision)
__device__ uint4 g_sA16u[(size_t)NR*DA/8];
__device__ uint4 g_pV16u[NK*DV/8];           // bf16 proto_vision
__device__ uint4 g_pA16u[NK*DA/8];
__device__ uint4 g_Mv16u[NK*DA/8];           // bf16 proto_v @ W_a2v
__device__ uint4 g_Ma16u[NK*DV/8];
__device__ float g_partials[NBLOCKS];

#define G_FV16 ((__nv_bfloat16*)g_fV16u)
#define G_FA16 ((__nv_bfloat16*)g_fA16u)
#define G_SV16 ((__nv_bfloat16*)g_sV16u)
#define G_SA16 ((__nv_bfloat16*)g_sA16u)
#define G_PV16 ((__nv_bfloat16*)g_pV16u)
#define G_PA16 ((__nv_bfloat16*)g_pA16u)
#define G_MV16 ((__nv_bfloat16*)g_Mv16u)
#define G_MA16 ((__nv_bfloat16*)g_Ma16u)

// ---------------- helpers ----------------
__device__ __forceinline__ uint32_t smem_u32(const void* p) {
    uint32_t a;
    asm("{ .reg .u64 t; cvta.to.shared.u64 t, %1; cvt.u32.u64 %0, t; }" : "=r"(a) : "l"(p));
    return a;
}
__device__ __forceinline__ void cp16(uint32_t dst, const void* src) {
    asm volatile("cp.async.cg.shared.global [%0], [%1], 16;" :: "r"(dst), "l"(src) : "memory");
}
__device__ __forceinline__ void cp_commit() {
    asm volatile("cp.async.commit_group;" ::: "memory");
}
__device__ __forceinline__ void cp_wait1() {
    asm volatile("cp.async.wait_group 1;" ::: "memory");
}
__device__ __forceinline__ void cp_wait0() {
    asm volatile("cp.async.wait_group 0;" ::: "memory");
}
__device__ __forceinline__ void ldsm4(uint32_t* r, uint32_t addr) {
    asm volatile("ldmatrix.sync.aligned.m8n8.x4.shared.b16 {%0,%1,%2,%3}, [%4];"
                 : "=r"(r[0]), "=r"(r[1]), "=r"(r[2]), "=r"(r[3]) : "r"(addr));
}
__device__ __forceinline__ void ldsm2(uint32_t* r, uint32_t addr) {
    asm volatile("ldmatrix.sync.aligned.m8n8.x2.shared.b16 {%0,%1}, [%2];"
                 : "=r"(r[0]), "=r"(r[1]) : "r"(addr));
}
__device__ __forceinline__ void mma16816(float* c, const uint32_t* a, const uint32_t* b) {
    asm volatile(
        "mma.sync.aligned.m16n8k16.row.col.f32.bf16.bf16.f32 "
        "{%0,%1,%2,%3}, {%4,%5,%6,%7}, {%8,%9}, {%0,%1,%2,%3};"
        : "+f"(c[0]), "+f"(c[1]), "+f"(c[2]), "+f"(c[3])
        : "r"(a[0]), "r"(a[1]), "r"(a[2]), "r"(a[3]), "r"(b[0]), "r"(b[1]));
}
__device__ __forceinline__ uint2 cvt4(float4 v) {
    __nv_bfloat162 lo = __floats2bfloat162_rn(v.x, v.y);
    __nv_bfloat162 hi = __floats2bfloat162_rn(v.z, v.w);
    uint2 r;
    r.x = *reinterpret_cast<uint32_t*>(&lo);
    r.y = *reinterpret_cast<uint32_t*>(&hi);
    return r;
}

// ---------------------------------------------------------------------------
// MEGA prologue: all independent prep in ONE launch (overlaps latency-bound
// proto GEMM with bandwidth-bound smooth). blockIdx.z partitions:
//   z=0: smooth+cvt vision       (R11-validated body, grid-stride)
//   z=1: smooth+cvt audio        (R11-validated body, grid-stride)
//   z=2: both proto GEMMs        (R11-validated body; flat-decoded block idx;
//                                 bf16 store = identical value to old fp32+cvt)
//   z=3: proto fp32->bf16 cvt    (R9-validated segments, protos only)
// block = 256 threads flat; grid.x = 3072.
// ---------------------------------------------------------------------------
__global__ void mega_prologue_kernel(const float* __restrict__ fvin,
                                     const float* __restrict__ fain,
                                     const float* __restrict__ pv,
                                     const float* __restrict__ pa,
                                     const float* __restrict__ wav,
                                     const float* __restrict__ wva)
{
    __shared__ float As[16][16];
    __shared__ float Ws[16][17];

    const int zpart = blockIdx.z;

    if (zpart < 2) {
        // ---- smooth + cvt (identical to smooth_all_kernel body) ----
        const int vz = (zpart == 0);
        const float* f = vz ? fvin : fain;
        const int D = vz ? DV : DA;
        uint2* __restrict__ s16 = reinterpret_cast<uint2*>(vz ? G_SV16 : G_SA16);
        uint2* __restrict__ f16 = reinterpret_cast<uint2*>(vz ? G_FV16 : G_FA16);
        const float4* __restrict__ fv = reinterpret_cast<const float4*>(f);
        const int D4 = D >> 2;
        const long total = (long)NR * D4;
        const float inv3 = 1.0f / 3.0f;
        for (long i = (long)blockIdx.x*blockDim.x + threadIdx.x; i < total;
             i += (long)gridDim.x*blockDim.x) {
            long row = i / D4;
            int s = (int)(row % NS);
            float4 c = fv[i];
            float4 r;
            if (s == 0) {
                float4 n = fv[i + D4];
                r.x=(c.x+n.x)*0.5f; r.y=(c.y+n.y)*0.5f;
                r.z=(c.z+n.z)*0.5f; r.w=(c.w+n.w)*0.5f;
            } else if (s == NS-1) {
                float4 p = fv[i - D4];
                r.x=(c.x+p.x)*0.5f; r.y=(c.y+p.y)*0.5f;
                r.z=(c.z+p.z)*0.5f; r.w=(c.w+p.w)*0.5f;
            } else {
                float4 p = fv[i - D4];
                float4 n = fv[i + D4];
                r.x=(p.x+c.x+n.x)*inv3; r.y=(p.y+c.y+n.y)*inv3;
                r.z=(p.z+c.z+n.z)*inv3; r.w=(p.w+c.w+n.w)*inv3;
            }
            s16[i] = cvt4(r);
            f16[i] = cvt4(c);
        }
    } else if (zpart == 2) {
        // ---- proto GEMMs (identical arithmetic to proto_all_kernel) ----
        // flat decode of (bx in [0,48), by in [0,32), za in {0,1})
        int lin = blockIdx.x;
        if (lin >= 48*32*2) return;
        int bx = lin % 48;
        int by = (lin / 48) % 32;
        int za = lin / (48*32);
        if (!za && bx >= DA/16) return;          // uniform per block, pre-sync
        const float* __restrict__ P = za ? pa : pv;
        const float* __restrict__ W = za ? wva : wav;
        const int D = za ? DA : DV;
        const int C = za ? DV : DA;
        __nv_bfloat16* __restrict__ Cout = za ? G_MA16 : G_MV16;

        int tx = threadIdx.x & 15;               // == old threadIdx.x
        int ty = threadIdx.x >> 4;               // == old threadIdx.y
        int row = by*16 + ty;
        int col = bx*16 + tx;
        float acc = 0.f;
        for (int d0 = 0; d0 < D; d0 += 16) {
            As[ty][tx] = P[row*D + d0 + tx];
            Ws[ty][tx] = W[(d0+ty)*C + col];
            __syncthreads();
            #pragma unroll
            for (int kk = 0; kk < 16; kk++) acc += As[ty][kk]*Ws[kk][tx];
            __syncthreads();
        }
        // same value as old (fp32 store -> later __float2bfloat16): one rounding
        Cout[row*C + col] = __float2bfloat16(acc);
    } else {
        // ---- proto fp32 -> bf16 (segments identical to cvt_all protos) ----
        const int nPV = NK*DV, nPA = NK*DA;
        const int total = nPV + nPA;
        for (int i = blockIdx.x*blockDim.x + threadIdx.x; i < total;
             i += gridDim.x*blockDim.x) {
            if (i < nPV) G_PV16[i] = __float2bfloat16(pv[i]);
            else         G_PA16[i-nPV] = __float2bfloat16(pa[i-nPV]);
        }
    }
}

// no-op filler (keeps 5-launch layout -> ncu keeps capturing the fused kernel)
__global__ void noop_kernel() {}

// ---------------------------------------------------------------------------
// Fused HMMA energy kernel (R15-validated, unchanged).
// ---------------------------------------------------------------------------
extern __shared__ char dsm[];

__global__ __launch_bounds__(NTH, 2)
void fused_energy_kernel()
{
    __shared__ float red_s[8];

    const int tid = threadIdx.x;
    const int wid = tid >> 5;
    const int lane = tid & 31;
    const int z = blockIdx.z;
    const long row0 = (long)blockIdx.y * BM;
    const long col0 = (long)blockIdx.x * BN;

    // phase-1 (cross) sources, phase-2 (intra) sources
    const __nv_bfloat16 *Ax, *Bx, *Ai, *Bi;
    int Dx, Di;
    if (z == 0) { Ax = G_SA16; Bx = G_MV16; Dx = DA; Ai = G_FV16; Bi = G_PV16; Di = DV; }
    else        { Ax = G_SV16; Bx = G_MA16; Dx = DV; Ai = G_FA16; Bi = G_PA16; Di = DA; }
    const int n1 = Dx / BK;          // cross chunks (16 or 24, even)
    const int nch = n1 + Di / BK;    // 40

    const uint32_t base0 = smem_u32(dsm);

    auto load_chunk = [&](int c, int stage) {
        const __nv_bfloat16 *A, *B; int D, k0;
        if (c < n1) { A = Ax; B = Bx; D = Dx; k0 = c * BK; }
        else        { A = Ai; B = Bi; D = Di; k0 = (c - n1) * BK; }
        uint32_t base = base0 + stage * STGB;
        #pragma unroll
        for (int r = 0; r < 2; r++) {
            int u = tid + r * 256;
            int row = u >> 2, seg = u & 3;
            uint32_t d = base + (uint32_t)(row * 80 + seg * 16);
            cp16(d,         A + (row0 + row) * D + k0 + seg * 8);
            cp16(d + ATILE, B + (col0 + row) * D + k0 + seg * 8);
        }
    };
    auto load_pair = [&](int c) {
        load_chunk(c, c & (NSTAGE-1));
        if (c + 1 < nch) load_chunk(c + 1, (c + 1) & (NSTAGE-1));
        cp_commit();
    };

    const int wm = (wid >> 2) * 64;   // warp row base
    const int wn = (wid & 3) * 32;    // warp col base
    const int arow = wm + (lane & 7) + ((lane >> 3) & 1) * 8;
    const int acol = (lane >> 4) * 16;           // byte offset (k-half)
    const int l2 = lane & 15;
    const int brow = wn + (l2 & 7);
    const int bcol = ((l2 >> 3) & 1) * 16;

    auto compute_chunk = [&](int stage, float (&acc)[4][4][4]) {
        uint32_t sA = base0 + stage * STGB;
        uint32_t sB = sA + ATILE;
        #pragma unroll
        for (int ks = 0; ks < 2; ks++) {
            uint32_t a[4][4];
            #pragma unroll
            for (int i = 0; i < 4; i++)
                ldsm4(a[i], sA + (uint32_t)((arow + i * 16) * 80 + acol + ks * 32));
            uint32_t b[4][2];
            #pragma unroll
            for (int j = 0; j < 4; j++)
                ldsm2(b[j], sB + (uint32_t)((brow + j * 8) * 80 + bcol + ks * 32));
            #pragma unroll
            for (int i = 0; i < 4; i++)
                #pragma unroll
                for (int j = 0; j < 4; j++)
                    mma16816(acc[i][j], a[i], b[j]);
        }
    };

    float acc[4][4][4] = {};

    load_pair(0);
    load_pair(2);

    auto pipe_step = [&](int c, float (&a)[4][4][4]) {
        if (c + 2 < nch) cp_wait1(); else cp_wait0();
        __syncthreads();                  // pair c visible to all warps
        compute_chunk(c & (NSTAGE-1), a);
        if (c + 1 < nch) compute_chunk((c + 1) & (NSTAGE-1), a);
        __syncthreads();                  // all warps done reading pair c
        if (c + 4 < nch) load_pair(c + 4);
    };

    // ---- phase 1: cross chunks [0, n1) -> acc, staged as c2 ----
    for (int c = 0; c < n1; c += 2) pipe_step(c, acc);

    // ---- stage c2 = cross results as bf16 (thread-private slots) ----
    {
        uint32_t* c2b = reinterpret_cast<uint32_t*>(dsm + C2BUF) + tid * 32;
        int s = 0;
        #pragma unroll
        for (int i = 0; i < 4; i++)
            #pragma unroll
            for (int j = 0; j < 4; j++)
                #pragma unroll
                for (int r = 0; r < 4; r += 2) {
                    __nv_bfloat162 p = __floats2bfloat162_rn(acc[i][j][r], acc[i][j][r+1]);
                    c2b[s++] = *reinterpret_cast<uint32_t*>(&p);
                }
        #pragma unroll
        for (int i = 0; i < 4; i++)
            #pragma unroll
            for (int j = 0; j < 4; j++)
                #pragma unroll
                for (int r = 0; r < 4; r++) acc[i][j][r] = 0.f;
    }

    // ---- phase 2: intra chunks [n1, nch) -> acc ----
    for (int c = n1; c < nch; c += 2) pipe_step(c, acc);

    // ---- epilogue: c1 = acc (regs), c2 = staged bf16 ----
    float local = 0.f;
    {
        const uint32_t* c2b = reinterpret_cast<const uint32_t*>(dsm + C2BUF) + tid * 32;
        int s = 0;
        #pragma unroll
        for (int i = 0; i < 4; i++)
            #pragma unroll
            for (int j = 0; j < 4; j++)
                #pragma unroll
                for (int r = 0; r < 4; r += 2) {
                    uint32_t pk = c2b[s++];
                    __nv_bfloat162 p = *reinterpret_cast<const __nv_bfloat162*>(&pk);
                    float c2a = __bfloat162float(p.x);
                    float c2bv = __bfloat162float(p.y);
                    float c1a = acc[i][j][r];
                    float c1b = acc[i][j][r+1];
                    float sala = LAM * c2a * c2a + (1.0f - LAM) * c1a * c1a;
                    float salb = LAM * c2bv * c2bv + (1.0f - LAM) * c1b * c1b;
                    float xa = sala * c1a;
                    float xb = salb * c1b;
                    local += fmaxf(xa, 0.f) + log1pf(__expf(-fabsf(xa)));
                    local += fmaxf(xb, 0.f) + log1pf(__expf(-fabsf(xb)));
                }
    }
    #pragma unroll
    for (int o = 16; o > 0; o >>= 1)
        local += __shfl_xor_sync(0xFFFFFFFF, local, o);
    if (lane == 0) red_s[wid] = local;
    __syncthreads();
    if (tid == 0) {
        float s = 0.f;
        #pragma unroll
        for (int w = 0; w < 8; w++) s += red_s[w];
        g_partials[(z * gridDim.y + blockIdx.y) * gridDim.x + blockIdx.x] = s;
    }
}

// ---------------------------------------------------------------------------
// Deterministic final reduction
// ---------------------------------------------------------------------------
__global__ void final_reduce_kernel(float* __restrict__ out)
{
    __shared__ double red[256];
    double s = 0.0;
    for (int i = threadIdx.x; i < NBLOCKS; i += 256) s += (double)g_partials[i];
    red[threadIdx.x] = s;
    __syncthreads();
    for (int st = 128; st > 0; st >>= 1) {
        if (threadIdx.x < st) red[threadIdx.x] += red[threadIdx.x + st];
        __syncthreads();
    }
    if (threadIdx.x == 0) out[0] = (float)(-red[0]);
}

// ---------------------------------------------------------------------------
extern "C" void kernel_launch(void* const* d_in, const int* in_sizes, int n_in,
                              void* d_out, int out_size)
{
    const float* fv  = (const float*)d_in[0];   // (8,2048,768)
    const float* fa  = (const float*)d_in[1];   // (8,2048,512)
    const float* pv  = (const float*)d_in[2];   // (512,768)
    const float* pa  = (const float*)d_in[3];   // (512,512)
    const float* wav = (const float*)d_in[4];   // (768,512)
    const float* wva = (const float*)d_in[5];   // (512,768)
    float* out = (float*)d_out;

    cudaFuncSetAttribute(fused_energy_kernel,
                         cudaFuncAttributeMaxDynamicSharedMemorySize, FUSED_SMEM);

    // 5 launches, fused at index 3 (same layout as R11-R15 -> ncu captures fused)
    mega_prologue_kernel<<<dim3(3072, 1, 4), 256>>>(fv, fa, pv, pa, wav, wva);    // 0
    noop_kernel<<<1, 32>>>();                                                     // 1
    noop_kernel<<<1, 32>>>();                                                     // 2
    fused_energy_kernel<<<dim3(NK/BN, NR/BM, 2), NTH, FUSED_SMEM>>>();            // 3
    final_reduce_kernel<<<1, 256>>>(out);                                         // 4
}